// round 1
// baseline (speedup 1.0000x reference)
#include <cuda_runtime.h>

// Problem shape (fixed for this problem instance)
#define Bb   2
#define Vv   5
#define Cch  16
#define Hh   512
#define Ww   640
#define Nn   131072
#define BV   (Bb * Vv)

// Scratch: channel-last transposed feature maps (bv, h, w, c). 209.7 MB static.
__device__ float g_fmT[(size_t)BV * Hh * Ww * Cch];

// ---------------------------------------------------------------------------
// Pass 1: transpose (bv, c, h, w) -> (bv, h, w, c)
// Block (32,16): read 16 channel-rows of 32 consecutive w (coalesced 128B),
// write 512 contiguous floats (w-major, c fastest) coalesced.
// ---------------------------------------------------------------------------
__global__ __launch_bounds__(512) void transpose_kernel(const float* __restrict__ fm) {
    __shared__ float s[16][33];
    const int w0 = blockIdx.x * 32;
    const int h  = blockIdx.y;
    const int bv = blockIdx.z;
    const int x  = threadIdx.x;   // 0..31 (w)
    const int c  = threadIdx.y;   // 0..15 (channel)

    s[c][x] = fm[(((size_t)bv * Cch + c) * Hh + h) * Ww + (w0 + x)];
    __syncthreads();

    const int tid = c * 32 + x;
    const int wi  = tid >> 4;     // 0..31
    const int ci  = tid & 15;     // 0..15
    g_fmT[(((size_t)bv * Hh + h) * Ww + (w0 + wi)) * Cch + ci] = s[ci][wi];
}

// ---------------------------------------------------------------------------
// Pass 2: project + 5 bilinear samples + gradients.
// Quad-per-point: 4 lanes share one point, each lane owns 4 channels
// (one float4 per corner). 20 float4 gathers per lane, 5 float4 accumulators.
// ---------------------------------------------------------------------------
__device__ __forceinline__ void mkpair(float t, int lim,
                                       int& i0, int& i1, float& w0, float& w1) {
    float f0 = floorf(t);
    float a1 = t - f0;          // frac
    float a0 = 1.0f - a1;
    int x0 = (int)f0;
    int x1 = x0 + 1;
    w0 = (x0 >= 0 && x0 < lim) ? a0 : 0.0f;   // mask == reference valid
    w1 = (x1 >= 0 && x1 < lim) ? a1 : 0.0f;
    i0 = min(max(x0, 0), lim - 1);            // == reference clip
    i1 = min(max(x1, 0), lim - 1);
}

__device__ __forceinline__ float4 f4fma(float w, float4 v, float4 a) {
    a.x = fmaf(w, v.x, a.x);
    a.y = fmaf(w, v.y, a.y);
    a.z = fmaf(w, v.z, a.z);
    a.w = fmaf(w, v.w, a.w);
    return a;
}

__global__ __launch_bounds__(256) void fgf_kernel(
    const float* __restrict__ pts,   // (B, 3, N)
    const float* __restrict__ Kmat,  // (B, V, 3, 3)
    const float* __restrict__ Emat,  // (B, V, 3, 4)
    float* __restrict__ out)         // [f (BV*C*N)] [f_grad (BV*C*N*2)]
{
    const int lane4 = threadIdx.x & 3;
    const int n  = blockIdx.x * 64 + (threadIdx.x >> 2);
    const int bv = blockIdx.y;
    const int b  = bv / Vv;

    // point
    const float px = __ldg(&pts[((size_t)b * 3 + 0) * Nn + n]);
    const float py = __ldg(&pts[((size_t)b * 3 + 1) * Nn + n]);
    const float pz = __ldg(&pts[((size_t)b * 3 + 2) * Nn + n]);

    const float* E = Emat + (size_t)bv * 12;
    const float* K = Kmat + (size_t)bv * 9;

    // tp = E[:, :3] @ p + E[:, 3]
    const float X = fmaf(__ldg(E + 0), px, fmaf(__ldg(E + 1), py, fmaf(__ldg(E + 2),  pz, __ldg(E + 3))));
    const float Y = fmaf(__ldg(E + 4), px, fmaf(__ldg(E + 5), py, fmaf(__ldg(E + 6),  pz, __ldg(E + 7))));
    const float Z = fmaf(__ldg(E + 8), px, fmaf(__ldg(E + 9), py, fmaf(__ldg(E + 10), pz, __ldg(E + 11))));

    const float invz = 1.0f / Z;
    const float xn = X * invz;
    const float yn = Y * invz;

    // uv = [xn, yn, 1] dot K rows
    const float u = fmaf(__ldg(K + 0), xn, fmaf(__ldg(K + 1), yn, __ldg(K + 2)));
    const float v = fmaf(__ldg(K + 3), xn, fmaf(__ldg(K + 4), yn, __ldg(K + 5)));

    // grid coords + neighbor shifts (match reference op order)
    const float gx = (u - 0.5f) / (float)(Ww - 1) * 2.0f - 1.0f;
    const float gy = (v - 0.5f) / (float)(Hh - 1) * 2.0f - 1.0f;
    const float dx = 2.0f / (float)(Ww - 1);
    const float dy = 2.0f / (float)(Hh - 1);

    const float ixc = ((gx        + 1.0f) * (float)Ww - 1.0f) * 0.5f;
    const float ixl = (((gx - dx) + 1.0f) * (float)Ww - 1.0f) * 0.5f;
    const float ixr = (((gx + dx) + 1.0f) * (float)Ww - 1.0f) * 0.5f;
    const float iyc = ((gy        + 1.0f) * (float)Hh - 1.0f) * 0.5f;
    const float iyt = (((gy - dy) + 1.0f) * (float)Hh - 1.0f) * 0.5f;
    const float iyb = (((gy + dy) + 1.0f) * (float)Hh - 1.0f) * 0.5f;

    int xc0, xc1, xl0, xl1, xr0, xr1;
    int yc0, yc1, yt0, yt1, yb0, yb1;
    float wxc0, wxc1, wxl0, wxl1, wxr0, wxr1;
    float wyc0, wyc1, wyt0, wyt1, wyb0, wyb1;
    mkpair(ixc, Ww, xc0, xc1, wxc0, wxc1);
    mkpair(ixl, Ww, xl0, xl1, wxl0, wxl1);
    mkpair(ixr, Ww, xr0, xr1, wxr0, wxr1);
    mkpair(iyc, Hh, yc0, yc1, wyc0, wyc1);
    mkpair(iyt, Hh, yt0, yt1, wyt0, wyt1);
    mkpair(iyb, Hh, yb0, yb1, wyb0, wyb1);

    // float4 addressing into (bv, h, w, c): float4 idx = bv*H*W*4 + (y*W+x)*4 + lane4
    const float4* base = reinterpret_cast<const float4*>(g_fmT)
                       + (size_t)bv * ((size_t)Hh * Ww * 4) + lane4;
    const int ryc0 = yc0 * (Ww * 4), ryc1 = yc1 * (Ww * 4);
    const int ryt0 = yt0 * (Ww * 4), ryt1 = yt1 * (Ww * 4);
    const int ryb0 = yb0 * (Ww * 4), ryb1 = yb1 * (Ww * 4);
    const int cxc0 = xc0 * 4, cxc1 = xc1 * 4;
    const int cxl0 = xl0 * 4, cxl1 = xl1 * 4;
    const int cxr0 = xr0 * 4, cxr1 = xr1 * 4;

    float4 F  = make_float4(0.f, 0.f, 0.f, 0.f);
    float4 FL = F, FR = F, FT = F, FB = F;

    // center
    F  = f4fma(wyc0 * wxc0, __ldg(base + ryc0 + cxc0), F);
    F  = f4fma(wyc0 * wxc1, __ldg(base + ryc0 + cxc1), F);
    F  = f4fma(wyc1 * wxc0, __ldg(base + ryc1 + cxc0), F);
    F  = f4fma(wyc1 * wxc1, __ldg(base + ryc1 + cxc1), F);
    // left
    FL = f4fma(wyc0 * wxl0, __ldg(base + ryc0 + cxl0), FL);
    FL = f4fma(wyc0 * wxl1, __ldg(base + ryc0 + cxl1), FL);
    FL = f4fma(wyc1 * wxl0, __ldg(base + ryc1 + cxl0), FL);
    FL = f4fma(wyc1 * wxl1, __ldg(base + ryc1 + cxl1), FL);
    // right
    FR = f4fma(wyc0 * wxr0, __ldg(base + ryc0 + cxr0), FR);
    FR = f4fma(wyc0 * wxr1, __ldg(base + ryc0 + cxr1), FR);
    FR = f4fma(wyc1 * wxr0, __ldg(base + ryc1 + cxr0), FR);
    FR = f4fma(wyc1 * wxr1, __ldg(base + ryc1 + cxr1), FR);
    // top
    FT = f4fma(wyt0 * wxc0, __ldg(base + ryt0 + cxc0), FT);
    FT = f4fma(wyt0 * wxc1, __ldg(base + ryt0 + cxc1), FT);
    FT = f4fma(wyt1 * wxc0, __ldg(base + ryt1 + cxc0), FT);
    FT = f4fma(wyt1 * wxc1, __ldg(base + ryt1 + cxc1), FT);
    // bottom
    FB = f4fma(wyb0 * wxc0, __ldg(base + ryb0 + cxc0), FB);
    FB = f4fma(wyb0 * wxc1, __ldg(base + ryb0 + cxc1), FB);
    FB = f4fma(wyb1 * wxc0, __ldg(base + ryb1 + cxc0), FB);
    FB = f4fma(wyb1 * wxc1, __ldg(base + ryb1 + cxc1), FB);

    // gradients
    float4 GX, GY;
    GX.x = 0.5f * (FR.x - FL.x); GX.y = 0.5f * (FR.y - FL.y);
    GX.z = 0.5f * (FR.z - FL.z); GX.w = 0.5f * (FR.w - FL.w);
    GY.x = 0.5f * (FB.x - FT.x); GY.y = 0.5f * (FB.y - FT.y);
    GY.z = 0.5f * (FB.z - FT.z); GY.w = 0.5f * (FB.w - FT.w);

    // f output: (bv, c, n); this lane owns channels lane4*4 .. +3
    const size_t fb = ((size_t)bv * Cch + (size_t)lane4 * 4) * Nn + n;
    out[fb + 0 * (size_t)Nn] = F.x;
    out[fb + 1 * (size_t)Nn] = F.y;
    out[fb + 2 * (size_t)Nn] = F.z;
    out[fb + 3 * (size_t)Nn] = F.w;

    // f_grad output: (bv, c, n, 2) -> float2 per (c, n)
    float2* og = reinterpret_cast<float2*>(out + (size_t)BV * Cch * Nn)
               + ((size_t)bv * Cch + (size_t)lane4 * 4) * Nn + n;
    og[0 * (size_t)Nn] = make_float2(GX.x, GY.x);
    og[1 * (size_t)Nn] = make_float2(GX.y, GY.y);
    og[2 * (size_t)Nn] = make_float2(GX.z, GY.z);
    og[3 * (size_t)Nn] = make_float2(GX.w, GY.w);
}

// ---------------------------------------------------------------------------
extern "C" void kernel_launch(void* const* d_in, const int* in_sizes, int n_in,
                              void* d_out, int out_size) {
    // Identify inputs robustly by element count.
    const float* fm  = nullptr;
    const float* pts = nullptr;
    const float* K   = nullptr;
    const float* E   = nullptr;
    for (int i = 0; i < n_in; i++) {
        switch (in_sizes[i]) {
            case Bb * Vv * Cch * Hh * Ww: fm  = (const float*)d_in[i]; break;  // 52428800
            case Bb * 3 * Nn:             pts = (const float*)d_in[i]; break;  // 786432
            case Bb * Vv * 9:             K   = (const float*)d_in[i]; break;  // 90
            case Bb * Vv * 12:            E   = (const float*)d_in[i]; break;  // 120
            default: break;
        }
    }

    dim3 tb(32, 16);
    dim3 tg(Ww / 32, Hh, BV);
    transpose_kernel<<<tg, tb>>>(fm);

    dim3 mg(Nn / 64, BV);
    fgf_kernel<<<mg, 256>>>(pts, K, E, (float*)d_out);
}

// round 4
// speedup vs baseline: 1.5175x; 1.5175x over previous
#include <cuda_runtime.h>

// Problem shape (fixed for this problem instance)
#define Bb   2
#define Vv   5
#define Cch  16
#define Hh   512
#define Ww   640
#define Nn   131072
#define BV   (Bb * Vv)

// Scratch: channel-last transposed feature maps (bv, h, w, c). 209.7 MB static.
__device__ float g_fmT[(size_t)BV * Hh * Ww * Cch];

// ---------------------------------------------------------------------------
// Pass 1: transpose (bv, c, h, w) -> (bv, h, w, c) via in-quad shuffle 4x4
// transpose. No shared memory, no barriers. Each lane: 1 LDG.128 (4 w, 1 c),
// 4 shfl_xor, 1 STG.128 (4 c, 1 w). Warp covers 8 w x 16 c; both the read
// and write sides are sector-optimal (16 x 32B sectors per instruction).
// ---------------------------------------------------------------------------
__global__ __launch_bounds__(256) void transpose_kernel(const float* __restrict__ fm) {
    const int lane = threadIdx.x & 31;
    const int warp = threadIdx.x >> 5;      // 0..7
    const int k    = lane & 3;              // row within 4x4 block
    const int q    = lane >> 2;             // quad id 0..7
    const int cg   = q & 3;                 // channel group (4 channels each)
    const int xg   = q >> 2;                // 0/1: which 4-w group
    const int c    = cg * 4 + k;            // this lane's channel
    const int bv   = blockIdx.z;
    const int wb   = blockIdx.x * 64 + warp * 8 + xg * 4;

    const float4* fm4  = reinterpret_cast<const float4*>(fm);
    float4*       out4 = reinterpret_cast<float4*>(g_fmT);

    #pragma unroll
    for (int i = 0; i < 2; i++) {
        const int h = blockIdx.y * 2 + i;
        // load: 4 consecutive w at channel c
        float4 v = __ldg(&fm4[((((size_t)bv * Cch + c) * Hh + h) * Ww + wb) >> 2]);

        // 4x4 transpose across the quad (lanes k=0..3)
        float2 lo = make_float2(v.x, v.y);
        float2 hi = make_float2(v.z, v.w);
        // round 1: exchange 2x2 sub-blocks across bit1
        {
            float2 snd = (k & 2) ? lo : hi;
            float2 rcv;
            rcv.x = __shfl_xor_sync(0xffffffffu, snd.x, 2);
            rcv.y = __shfl_xor_sync(0xffffffffu, snd.y, 2);
            if (k & 2) lo = rcv; else hi = rcv;
        }
        // round 2: exchange elements across bit0
        {
            float2 snd = (k & 1) ? make_float2(lo.x, hi.x) : make_float2(lo.y, hi.y);
            float2 rcv;
            rcv.x = __shfl_xor_sync(0xffffffffu, snd.x, 1);
            rcv.y = __shfl_xor_sync(0xffffffffu, snd.y, 1);
            if (k & 1) { lo.x = rcv.x; hi.x = rcv.y; }
            else       { lo.y = rcv.x; hi.y = rcv.y; }
        }
        // lane now holds channels cg*4..cg*4+3 at pixel w = wb + k
        float4 o = make_float4(lo.x, lo.y, hi.x, hi.y);
        out4[(((size_t)bv * Hh + h) * Ww + (wb + k)) * 4 + cg] = o;
    }
}

// ---------------------------------------------------------------------------
// Pass 2: project + 5 bilinear samples + gradients, with tap deduplication.
// Quad-per-point: 4 lanes share a point, each lane owns 4 channels.
// The +-dx/+-dy shifts are ~1.0016 px, so with ~99.8% probability
// xl1==xc0, xr0==xc1, yt1==yc0, yb0==yc1 -> only 12 unconditional float4
// gathers per lane (vs 20), plus 6 rarely-taken fallbacks.
// ---------------------------------------------------------------------------
__device__ __forceinline__ void mkpair(float t, int lim,
                                       int& i0, int& i1, float& w0, float& w1) {
    float f0 = floorf(t);
    float a1 = t - f0;          // frac
    float a0 = 1.0f - a1;
    int x0 = (int)f0;
    int x1 = x0 + 1;
    w0 = (x0 >= 0 && x0 < lim) ? a0 : 0.0f;   // mask == reference valid
    w1 = (x1 >= 0 && x1 < lim) ? a1 : 0.0f;
    i0 = min(max(x0, 0), lim - 1);            // == reference clip
    i1 = min(max(x1, 0), lim - 1);
}

__device__ __forceinline__ float4 f4fma(float w, float4 v, float4 a) {
    a.x = fmaf(w, v.x, a.x);
    a.y = fmaf(w, v.y, a.y);
    a.z = fmaf(w, v.z, a.z);
    a.w = fmaf(w, v.w, a.w);
    return a;
}

__global__ __launch_bounds__(256) void fgf_kernel(
    const float* __restrict__ pts,   // (B, 3, N)
    const float* __restrict__ Kmat,  // (B, V, 3, 3)
    const float* __restrict__ Emat,  // (B, V, 3, 4)
    float* __restrict__ out)         // [f (BV*C*N)] [f_grad (BV*C*N*2)]
{
    const int lane4 = threadIdx.x & 3;
    const int n  = blockIdx.x * 64 + (threadIdx.x >> 2);
    const int bv = blockIdx.y;
    const int b  = bv / Vv;

    // point
    const float px = __ldg(&pts[((size_t)b * 3 + 0) * Nn + n]);
    const float py = __ldg(&pts[((size_t)b * 3 + 1) * Nn + n]);
    const float pz = __ldg(&pts[((size_t)b * 3 + 2) * Nn + n]);

    const float* E = Emat + (size_t)bv * 12;
    const float* K = Kmat + (size_t)bv * 9;

    // tp = E[:, :3] @ p + E[:, 3]
    const float X = fmaf(__ldg(E + 0), px, fmaf(__ldg(E + 1), py, fmaf(__ldg(E + 2),  pz, __ldg(E + 3))));
    const float Y = fmaf(__ldg(E + 4), px, fmaf(__ldg(E + 5), py, fmaf(__ldg(E + 6),  pz, __ldg(E + 7))));
    const float Z = fmaf(__ldg(E + 8), px, fmaf(__ldg(E + 9), py, fmaf(__ldg(E + 10), pz, __ldg(E + 11))));

    const float invz = 1.0f / Z;
    const float xn = X * invz;
    const float yn = Y * invz;

    // uv = [xn, yn, 1] dot K rows
    const float u = fmaf(__ldg(K + 0), xn, fmaf(__ldg(K + 1), yn, __ldg(K + 2)));
    const float v = fmaf(__ldg(K + 3), xn, fmaf(__ldg(K + 4), yn, __ldg(K + 5)));

    // grid coords + neighbor shifts (match reference op order)
    const float gx = (u - 0.5f) / (float)(Ww - 1) * 2.0f - 1.0f;
    const float gy = (v - 0.5f) / (float)(Hh - 1) * 2.0f - 1.0f;
    const float dx = 2.0f / (float)(Ww - 1);
    const float dy = 2.0f / (float)(Hh - 1);

    const float ixc = ((gx        + 1.0f) * (float)Ww - 1.0f) * 0.5f;
    const float ixl = (((gx - dx) + 1.0f) * (float)Ww - 1.0f) * 0.5f;
    const float ixr = (((gx + dx) + 1.0f) * (float)Ww - 1.0f) * 0.5f;
    const float iyc = ((gy        + 1.0f) * (float)Hh - 1.0f) * 0.5f;
    const float iyt = (((gy - dy) + 1.0f) * (float)Hh - 1.0f) * 0.5f;
    const float iyb = (((gy + dy) + 1.0f) * (float)Hh - 1.0f) * 0.5f;

    int xc0, xc1, xl0, xl1, xr0, xr1;
    int yc0, yc1, yt0, yt1, yb0, yb1;
    float wxc0, wxc1, wxl0, wxl1, wxr0, wxr1;
    float wyc0, wyc1, wyt0, wyt1, wyb0, wyb1;
    mkpair(ixc, Ww, xc0, xc1, wxc0, wxc1);
    mkpair(ixl, Ww, xl0, xl1, wxl0, wxl1);
    mkpair(ixr, Ww, xr0, xr1, wxr0, wxr1);
    mkpair(iyc, Hh, yc0, yc1, wyc0, wyc1);
    mkpair(iyt, Hh, yt0, yt1, wyt0, wyt1);
    mkpair(iyb, Hh, yb0, yb1, wyb0, wyb1);

    // float4 addressing into (bv, h, w, c): float4 idx = bv*H*W*4 + (y*W+x)*4 + lane4
    const float4* base = reinterpret_cast<const float4*>(g_fmT)
                       + (size_t)bv * ((size_t)Hh * Ww * 4) + lane4;
    const int ryc0 = yc0 * (Ww * 4), ryc1 = yc1 * (Ww * 4);
    const int ryt0 = yt0 * (Ww * 4);
    const int ryb1 = yb1 * (Ww * 4);
    const int cxc0 = xc0 * 4, cxc1 = xc1 * 4;
    const int cxl0 = xl0 * 4;
    const int cxr1 = xr1 * 4;

    // --- 12 unconditional unique taps ---
    const float4 a0 = __ldg(base + ryc0 + cxl0);   // (yc0, xl0)
    const float4 b0 = __ldg(base + ryc0 + cxc0);   // (yc0, xc0)
    const float4 c0 = __ldg(base + ryc0 + cxc1);   // (yc0, xc1)
    const float4 d0 = __ldg(base + ryc0 + cxr1);   // (yc0, xr1)
    const float4 a1 = __ldg(base + ryc1 + cxl0);   // (yc1, xl0)
    const float4 b1 = __ldg(base + ryc1 + cxc0);   // (yc1, xc0)
    const float4 c1 = __ldg(base + ryc1 + cxc1);   // (yc1, xc1)
    const float4 d1 = __ldg(base + ryc1 + cxr1);   // (yc1, xr1)
    const float4 t00 = __ldg(base + ryt0 + cxc0);  // (yt0, xc0)
    const float4 t01 = __ldg(base + ryt0 + cxc1);  // (yt0, xc1)
    const float4 q10 = __ldg(base + ryb1 + cxc0);  // (yb1, xc0)
    const float4 q11 = __ldg(base + ryb1 + cxc1);  // (yb1, xc1)

    // --- rare fallback taps (~0.2% each) ---
    float4 l1_0 = b0, l1_1 = b1;
    if (xl1 != xc0) {
        const int cxl1 = xl1 * 4;
        l1_0 = __ldg(base + ryc0 + cxl1);
        l1_1 = __ldg(base + ryc1 + cxl1);
    }
    float4 r0_0 = c0, r0_1 = c1;
    if (xr0 != xc1) {
        const int cxr0 = xr0 * 4;
        r0_0 = __ldg(base + ryc0 + cxr0);
        r0_1 = __ldg(base + ryc1 + cxr0);
    }
    float4 t10 = b0, t11 = c0;
    if (yt1 != yc0) {
        const int ryt1 = yt1 * (Ww * 4);
        t10 = __ldg(base + ryt1 + cxc0);
        t11 = __ldg(base + ryt1 + cxc1);
    }
    float4 u00 = b1, u01 = c1;
    if (yb0 != yc1) {
        const int ryb0 = yb0 * (Ww * 4);
        u00 = __ldg(base + ryb0 + cxc0);
        u01 = __ldg(base + ryb0 + cxc1);
    }

    float4 F  = make_float4(0.f, 0.f, 0.f, 0.f);
    float4 FL = F, FR = F, FT = F, FB = F;

    // center
    F  = f4fma(wyc0 * wxc0, b0, F);
    F  = f4fma(wyc0 * wxc1, c0, F);
    F  = f4fma(wyc1 * wxc0, b1, F);
    F  = f4fma(wyc1 * wxc1, c1, F);
    // left
    FL = f4fma(wyc0 * wxl0, a0,   FL);
    FL = f4fma(wyc0 * wxl1, l1_0, FL);
    FL = f4fma(wyc1 * wxl0, a1,   FL);
    FL = f4fma(wyc1 * wxl1, l1_1, FL);
    // right
    FR = f4fma(wyc0 * wxr0, r0_0, FR);
    FR = f4fma(wyc0 * wxr1, d0,   FR);
    FR = f4fma(wyc1 * wxr0, r0_1, FR);
    FR = f4fma(wyc1 * wxr1, d1,   FR);
    // top
    FT = f4fma(wyt0 * wxc0, t00, FT);
    FT = f4fma(wyt0 * wxc1, t01, FT);
    FT = f4fma(wyt1 * wxc0, t10, FT);
    FT = f4fma(wyt1 * wxc1, t11, FT);
    // bottom
    FB = f4fma(wyb0 * wxc0, u00, FB);
    FB = f4fma(wyb0 * wxc1, u01, FB);
    FB = f4fma(wyb1 * wxc0, q10, FB);
    FB = f4fma(wyb1 * wxc1, q11, FB);

    // gradients
    float4 GX, GY;
    GX.x = 0.5f * (FR.x - FL.x); GX.y = 0.5f * (FR.y - FL.y);
    GX.z = 0.5f * (FR.z - FL.z); GX.w = 0.5f * (FR.w - FL.w);
    GY.x = 0.5f * (FB.x - FT.x); GY.y = 0.5f * (FB.y - FT.y);
    GY.z = 0.5f * (FB.z - FT.z); GY.w = 0.5f * (FB.w - FT.w);

    // f output: (bv, c, n); this lane owns channels lane4*4 .. +3
    const size_t fb = ((size_t)bv * Cch + (size_t)lane4 * 4) * Nn + n;
    out[fb + 0 * (size_t)Nn] = F.x;
    out[fb + 1 * (size_t)Nn] = F.y;
    out[fb + 2 * (size_t)Nn] = F.z;
    out[fb + 3 * (size_t)Nn] = F.w;

    // f_grad output: (bv, c, n, 2) -> float2 per (c, n)
    float2* og = reinterpret_cast<float2*>(out + (size_t)BV * Cch * Nn)
               + ((size_t)bv * Cch + (size_t)lane4 * 4) * Nn + n;
    og[0 * (size_t)Nn] = make_float2(GX.x, GY.x);
    og[1 * (size_t)Nn] = make_float2(GX.y, GY.y);
    og[2 * (size_t)Nn] = make_float2(GX.z, GY.z);
    og[3 * (size_t)Nn] = make_float2(GX.w, GY.w);
}

// ---------------------------------------------------------------------------
extern "C" void kernel_launch(void* const* d_in, const int* in_sizes, int n_in,
                              void* d_out, int out_size) {
    // Identify inputs robustly by element count.
    const float* fm  = nullptr;
    const float* pts = nullptr;
    const float* K   = nullptr;
    const float* E   = nullptr;
    for (int i = 0; i < n_in; i++) {
        switch (in_sizes[i]) {
            case Bb * Vv * Cch * Hh * Ww: fm  = (const float*)d_in[i]; break;  // 52428800
            case Bb * 3 * Nn:             pts = (const float*)d_in[i]; break;  // 786432
            case Bb * Vv * 9:             K   = (const float*)d_in[i]; break;  // 90
            case Bb * Vv * 12:            E   = (const float*)d_in[i]; break;  // 120
            default: break;
        }
    }

    dim3 tg(Ww / 64, Hh / 2, BV);
    transpose_kernel<<<tg, 256>>>(fm);

    dim3 mg(Nn / 64, BV);
    fgf_kernel<<<mg, 256>>>(pts, K, E, (float*)d_out);
}

// round 8
// speedup vs baseline: 1.8062x; 1.1902x over previous
#include <cuda_runtime.h>
#include <cuda_fp16.h>

// Problem shape (fixed for this problem instance)
#define Bb   2
#define Vv   5
#define Cch  16
#define Hh   512
#define Ww   640
#define Nn   131072
#define BV   (Bb * Vv)

// Scratch: channel-last transposed feature maps (bv, h, w, c) in fp16. 104.9 MB.
__device__ __half g_fmT[(size_t)BV * Hh * Ww * Cch];

// ---------------------------------------------------------------------------
// Pass 1: transpose (bv, c, h, w) fp32 -> (bv, h, w, c) fp16, via in-quad
// shuffle 4x4 transpose. No smem, no barriers. Lane: 1 LDG.128, 4 shfl,
// cvt to fp16, 1 STG.64.
// ---------------------------------------------------------------------------
__global__ __launch_bounds__(256) void transpose_kernel(const float* __restrict__ fm) {
    const int lane = threadIdx.x & 31;
    const int warp = threadIdx.x >> 5;      // 0..7
    const int k    = lane & 3;              // row within 4x4 block
    const int q    = lane >> 2;             // quad id 0..7
    const int cg   = q & 3;                 // channel group (4 channels each)
    const int xg   = q >> 2;                // 0/1: which 4-w group
    const int c    = cg * 4 + k;            // this lane's channel
    const int bv   = blockIdx.z;
    const int wb   = blockIdx.x * 64 + warp * 8 + xg * 4;

    const float4* fm4  = reinterpret_cast<const float4*>(fm);
    uint2*        out2 = reinterpret_cast<uint2*>(g_fmT);

    #pragma unroll
    for (int i = 0; i < 2; i++) {
        const int h = blockIdx.y * 2 + i;
        // load: 4 consecutive w at channel c
        float4 v = __ldg(&fm4[((((size_t)bv * Cch + c) * Hh + h) * Ww + wb) >> 2]);

        // 4x4 transpose across the quad (lanes k=0..3)
        float2 lo = make_float2(v.x, v.y);
        float2 hi = make_float2(v.z, v.w);
        {
            float2 snd = (k & 2) ? lo : hi;
            float2 rcv;
            rcv.x = __shfl_xor_sync(0xffffffffu, snd.x, 2);
            rcv.y = __shfl_xor_sync(0xffffffffu, snd.y, 2);
            if (k & 2) lo = rcv; else hi = rcv;
        }
        {
            float2 snd = (k & 1) ? make_float2(lo.x, hi.x) : make_float2(lo.y, hi.y);
            float2 rcv;
            rcv.x = __shfl_xor_sync(0xffffffffu, snd.x, 1);
            rcv.y = __shfl_xor_sync(0xffffffffu, snd.y, 1);
            if (k & 1) { lo.x = rcv.x; hi.x = rcv.y; }
            else       { lo.y = rcv.x; hi.y = rcv.y; }
        }
        // lane now holds channels cg*4..cg*4+3 at pixel w = wb + k; pack fp16
        __half2 p0 = __floats2half2_rn(lo.x, lo.y);
        __half2 p1 = __floats2half2_rn(hi.x, hi.y);
        uint2 o;
        o.x = *reinterpret_cast<unsigned*>(&p0);
        o.y = *reinterpret_cast<unsigned*>(&p1);
        out2[(((size_t)bv * Hh + h) * Ww + (wb + k)) * 4 + cg] = o;
    }
}

// ---------------------------------------------------------------------------
// Pass 2: project + 5 bilinear samples + gradients, tap-dedup, fp16 gathers.
// Quad-per-point: 4 lanes share a point, each lane owns 4 channels (uint2 =
// 4 halves per tap). 12 unconditional taps + 6 rare (~0.2%) fallbacks.
// ---------------------------------------------------------------------------
__device__ __forceinline__ void mkpair(float t, int lim,
                                       int& i0, int& i1, float& w0, float& w1) {
    float f0 = floorf(t);
    float a1 = t - f0;          // frac
    float a0 = 1.0f - a1;
    int x0 = (int)f0;
    int x1 = x0 + 1;
    w0 = (x0 >= 0 && x0 < lim) ? a0 : 0.0f;   // mask == reference valid
    w1 = (x1 >= 0 && x1 < lim) ? a1 : 0.0f;
    i0 = min(max(x0, 0), lim - 1);            // == reference clip
    i1 = min(max(x1, 0), lim - 1);
}

__device__ __forceinline__ float4 h4f(uint2 p) {
    float2 a = __half22float2(*reinterpret_cast<__half2*>(&p.x));
    float2 b = __half22float2(*reinterpret_cast<__half2*>(&p.y));
    return make_float4(a.x, a.y, b.x, b.y);
}

__device__ __forceinline__ float4 f4fma(float w, uint2 pv, float4 a) {
    float4 v = h4f(pv);
    a.x = fmaf(w, v.x, a.x);
    a.y = fmaf(w, v.y, a.y);
    a.z = fmaf(w, v.z, a.z);
    a.w = fmaf(w, v.w, a.w);
    return a;
}

__global__ __launch_bounds__(256) void fgf_kernel(
    const float* __restrict__ pts,   // (B, 3, N)
    const float* __restrict__ Kmat,  // (B, V, 3, 3)
    const float* __restrict__ Emat,  // (B, V, 3, 4)
    float* __restrict__ out)         // [f (BV*C*N)] [f_grad (BV*C*N*2)]
{
    const int lane4 = threadIdx.x & 3;
    const int n  = blockIdx.x * 64 + (threadIdx.x >> 2);
    const int bv = blockIdx.y;
    const int b  = bv / Vv;

    // point
    const float px = __ldg(&pts[((size_t)b * 3 + 0) * Nn + n]);
    const float py = __ldg(&pts[((size_t)b * 3 + 1) * Nn + n]);
    const float pz = __ldg(&pts[((size_t)b * 3 + 2) * Nn + n]);

    const float* E = Emat + (size_t)bv * 12;
    const float* K = Kmat + (size_t)bv * 9;

    // tp = E[:, :3] @ p + E[:, 3]
    const float X = fmaf(__ldg(E + 0), px, fmaf(__ldg(E + 1), py, fmaf(__ldg(E + 2),  pz, __ldg(E + 3))));
    const float Y = fmaf(__ldg(E + 4), px, fmaf(__ldg(E + 5), py, fmaf(__ldg(E + 6),  pz, __ldg(E + 7))));
    const float Z = fmaf(__ldg(E + 8), px, fmaf(__ldg(E + 9), py, fmaf(__ldg(E + 10), pz, __ldg(E + 11))));

    const float invz = 1.0f / Z;
    const float xn = X * invz;
    const float yn = Y * invz;

    // uv = [xn, yn, 1] dot K rows
    const float u = fmaf(__ldg(K + 0), xn, fmaf(__ldg(K + 1), yn, __ldg(K + 2)));
    const float v = fmaf(__ldg(K + 3), xn, fmaf(__ldg(K + 4), yn, __ldg(K + 5)));

    // grid coords + neighbor shifts (match reference op order)
    const float gx = (u - 0.5f) / (float)(Ww - 1) * 2.0f - 1.0f;
    const float gy = (v - 0.5f) / (float)(Hh - 1) * 2.0f - 1.0f;
    const float dx = 2.0f / (float)(Ww - 1);
    const float dy = 2.0f / (float)(Hh - 1);

    const float ixc = ((gx        + 1.0f) * (float)Ww - 1.0f) * 0.5f;
    const float ixl = (((gx - dx) + 1.0f) * (float)Ww - 1.0f) * 0.5f;
    const float ixr = (((gx + dx) + 1.0f) * (float)Ww - 1.0f) * 0.5f;
    const float iyc = ((gy        + 1.0f) * (float)Hh - 1.0f) * 0.5f;
    const float iyt = (((gy - dy) + 1.0f) * (float)Hh - 1.0f) * 0.5f;
    const float iyb = (((gy + dy) + 1.0f) * (float)Hh - 1.0f) * 0.5f;

    int xc0, xc1, xl0, xl1, xr0, xr1;
    int yc0, yc1, yt0, yt1, yb0, yb1;
    float wxc0, wxc1, wxl0, wxl1, wxr0, wxr1;
    float wyc0, wyc1, wyt0, wyt1, wyb0, wyb1;
    mkpair(ixc, Ww, xc0, xc1, wxc0, wxc1);
    mkpair(ixl, Ww, xl0, xl1, wxl0, wxl1);
    mkpair(ixr, Ww, xr0, xr1, wxr0, wxr1);
    mkpair(iyc, Hh, yc0, yc1, wyc0, wyc1);
    mkpair(iyt, Hh, yt0, yt1, wyt0, wyt1);
    mkpair(iyb, Hh, yb0, yb1, wyb0, wyb1);

    // uint2 addressing into (bv, h, w, c): idx = bv*H*W*4 + (y*W+x)*4 + lane4
    const uint2* base = reinterpret_cast<const uint2*>(g_fmT)
                      + (size_t)bv * ((size_t)Hh * Ww * 4) + lane4;
    const int ryc0 = yc0 * (Ww * 4), ryc1 = yc1 * (Ww * 4);
    const int ryt0 = yt0 * (Ww * 4);
    const int ryb1 = yb1 * (Ww * 4);
    const int cxc0 = xc0 * 4, cxc1 = xc1 * 4;
    const int cxl0 = xl0 * 4;
    const int cxr1 = xr1 * 4;

    // --- 12 unconditional unique taps ---
    const uint2 a0 = __ldg(base + ryc0 + cxl0);   // (yc0, xl0)
    const uint2 b0 = __ldg(base + ryc0 + cxc0);   // (yc0, xc0)
    const uint2 c0 = __ldg(base + ryc0 + cxc1);   // (yc0, xc1)
    const uint2 d0 = __ldg(base + ryc0 + cxr1);   // (yc0, xr1)
    const uint2 a1 = __ldg(base + ryc1 + cxl0);   // (yc1, xl0)
    const uint2 b1 = __ldg(base + ryc1 + cxc0);   // (yc1, xc0)
    const uint2 c1 = __ldg(base + ryc1 + cxc1);   // (yc1, xc1)
    const uint2 d1 = __ldg(base + ryc1 + cxr1);   // (yc1, xr1)
    const uint2 t00 = __ldg(base + ryt0 + cxc0);  // (yt0, xc0)
    const uint2 t01 = __ldg(base + ryt0 + cxc1);  // (yt0, xc1)
    const uint2 q10 = __ldg(base + ryb1 + cxc0);  // (yb1, xc0)
    const uint2 q11 = __ldg(base + ryb1 + cxc1);  // (yb1, xc1)

    // --- rare fallback taps (~0.2% each) ---
    uint2 l1_0 = b0, l1_1 = b1;
    if (xl1 != xc0) {
        const int cxl1 = xl1 * 4;
        l1_0 = __ldg(base + ryc0 + cxl1);
        l1_1 = __ldg(base + ryc1 + cxl1);
    }
    uint2 r0_0 = c0, r0_1 = c1;
    if (xr0 != xc1) {
        const int cxr0 = xr0 * 4;
        r0_0 = __ldg(base + ryc0 + cxr0);
        r0_1 = __ldg(base + ryc1 + cxr0);
    }
    uint2 t10 = b0, t11 = c0;
    if (yt1 != yc0) {
        const int ryt1 = yt1 * (Ww * 4);
        t10 = __ldg(base + ryt1 + cxc0);
        t11 = __ldg(base + ryt1 + cxc1);
    }
    uint2 u00 = b1, u01 = c1;
    if (yb0 != yc1) {
        const int ryb0 = yb0 * (Ww * 4);
        u00 = __ldg(base + ryb0 + cxc0);
        u01 = __ldg(base + ryb0 + cxc1);
    }

    float4 F  = make_float4(0.f, 0.f, 0.f, 0.f);
    float4 FL = F, FR = F, FT = F, FB = F;

    // center
    F  = f4fma(wyc0 * wxc0, b0, F);
    F  = f4fma(wyc0 * wxc1, c0, F);
    F  = f4fma(wyc1 * wxc0, b1, F);
    F  = f4fma(wyc1 * wxc1, c1, F);
    // left
    FL = f4fma(wyc0 * wxl0, a0,   FL);
    FL = f4fma(wyc0 * wxl1, l1_0, FL);
    FL = f4fma(wyc1 * wxl0, a1,   FL);
    FL = f4fma(wyc1 * wxl1, l1_1, FL);
    // right
    FR = f4fma(wyc0 * wxr0, r0_0, FR);
    FR = f4fma(wyc0 * wxr1, d0,   FR);
    FR = f4fma(wyc1 * wxr0, r0_1, FR);
    FR = f4fma(wyc1 * wxr1, d1,   FR);
    // top
    FT = f4fma(wyt0 * wxc0, t00, FT);
    FT = f4fma(wyt0 * wxc1, t01, FT);
    FT = f4fma(wyt1 * wxc0, t10, FT);
    FT = f4fma(wyt1 * wxc1, t11, FT);
    // bottom
    FB = f4fma(wyb0 * wxc0, u00, FB);
    FB = f4fma(wyb0 * wxc1, u01, FB);
    FB = f4fma(wyb1 * wxc0, q10, FB);
    FB = f4fma(wyb1 * wxc1, q11, FB);

    // gradients
    float4 GX, GY;
    GX.x = 0.5f * (FR.x - FL.x); GX.y = 0.5f * (FR.y - FL.y);
    GX.z = 0.5f * (FR.z - FL.z); GX.w = 0.5f * (FR.w - FL.w);
    GY.x = 0.5f * (FB.x - FT.x); GY.y = 0.5f * (FB.y - FT.y);
    GY.z = 0.5f * (FB.z - FT.z); GY.w = 0.5f * (FB.w - FT.w);

    // f output: (bv, c, n); this lane owns channels lane4*4 .. +3
    const size_t fb = ((size_t)bv * Cch + (size_t)lane4 * 4) * Nn + n;
    __stcs(&out[fb + 0 * (size_t)Nn], F.x);
    __stcs(&out[fb + 1 * (size_t)Nn], F.y);
    __stcs(&out[fb + 2 * (size_t)Nn], F.z);
    __stcs(&out[fb + 3 * (size_t)Nn], F.w);

    // f_grad output: (bv, c, n, 2) -> float2 per (c, n)
    float2* og = reinterpret_cast<float2*>(out + (size_t)BV * Cch * Nn)
               + ((size_t)bv * Cch + (size_t)lane4 * 4) * Nn + n;
    __stcs(&og[0 * (size_t)Nn], make_float2(GX.x, GY.x));
    __stcs(&og[1 * (size_t)Nn], make_float2(GX.y, GY.y));
    __stcs(&og[2 * (size_t)Nn], make_float2(GX.z, GY.z));
    __stcs(&og[3 * (size_t)Nn], make_float2(GX.w, GY.w));
}

// ---------------------------------------------------------------------------
extern "C" void kernel_launch(void* const* d_in, const int* in_sizes, int n_in,
                              void* d_out, int out_size) {
    // Identify inputs robustly by element count.
    const float* fm  = nullptr;
    const float* pts = nullptr;
    const float* K   = nullptr;
    const float* E   = nullptr;
    for (int i = 0; i < n_in; i++) {
        switch (in_sizes[i]) {
            case Bb * Vv * Cch * Hh * Ww: fm  = (const float*)d_in[i]; break;  // 52428800
            case Bb * 3 * Nn:             pts = (const float*)d_in[i]; break;  // 786432
            case Bb * Vv * 9:             K   = (const float*)d_in[i]; break;  // 90
            case Bb * Vv * 12:            E   = (const float*)d_in[i]; break;  // 120
            default: break;
        }
    }

    dim3 tg(Ww / 64, Hh / 2, BV);
    transpose_kernel<<<tg, 256>>>(fm);

    dim3 mg(Nn / 64, BV);
    fgf_kernel<<<mg, 256>>>(pts, K, E, (float*)d_out);
}

// round 12
// speedup vs baseline: 1.9549x; 1.0823x over previous
#include <cuda_runtime.h>
#include <cuda_fp16.h>

// Problem shape (fixed for this problem instance)
#define Bb   2
#define Vv   5
#define Cch  16
#define Hh   512
#define Ww   640
#define Nn   131072
#define BV   (Bb * Vv)

// Scratch: channel-last transposed feature maps (bv, h, w, c) in fp16. 104.9 MB.
__device__ __half g_fmT[(size_t)BV * Hh * Ww * Cch];

// ---------------------------------------------------------------------------
// Pass 1: transpose (bv, c, h, w) fp32 -> (bv, h, w, c) fp16, via in-quad
// shuffle 4x4 transpose. No smem, no barriers.
// ---------------------------------------------------------------------------
__global__ __launch_bounds__(256) void transpose_kernel(const float* __restrict__ fm) {
    const int lane = threadIdx.x & 31;
    const int warp = threadIdx.x >> 5;      // 0..7
    const int k    = lane & 3;              // row within 4x4 block
    const int q    = lane >> 2;             // quad id 0..7
    const int cg   = q & 3;                 // channel group (4 channels each)
    const int xg   = q >> 2;                // 0/1: which 4-w group
    const int c    = cg * 4 + k;            // this lane's channel
    const int bv   = blockIdx.z;
    const int wb   = blockIdx.x * 64 + warp * 8 + xg * 4;

    const float4* fm4  = reinterpret_cast<const float4*>(fm);
    uint2*        out2 = reinterpret_cast<uint2*>(g_fmT);

    #pragma unroll
    for (int i = 0; i < 2; i++) {
        const int h = blockIdx.y * 2 + i;
        float4 v = __ldg(&fm4[((((size_t)bv * Cch + c) * Hh + h) * Ww + wb) >> 2]);

        float2 lo = make_float2(v.x, v.y);
        float2 hi = make_float2(v.z, v.w);
        {
            float2 snd = (k & 2) ? lo : hi;
            float2 rcv;
            rcv.x = __shfl_xor_sync(0xffffffffu, snd.x, 2);
            rcv.y = __shfl_xor_sync(0xffffffffu, snd.y, 2);
            if (k & 2) lo = rcv; else hi = rcv;
        }
        {
            float2 snd = (k & 1) ? make_float2(lo.x, hi.x) : make_float2(lo.y, hi.y);
            float2 rcv;
            rcv.x = __shfl_xor_sync(0xffffffffu, snd.x, 1);
            rcv.y = __shfl_xor_sync(0xffffffffu, snd.y, 1);
            if (k & 1) { lo.x = rcv.x; hi.x = rcv.y; }
            else       { lo.y = rcv.x; hi.y = rcv.y; }
        }
        __half2 p0 = __floats2half2_rn(lo.x, lo.y);
        __half2 p1 = __floats2half2_rn(hi.x, hi.y);
        uint2 o;
        o.x = *reinterpret_cast<unsigned*>(&p0);
        o.y = *reinterpret_cast<unsigned*>(&p1);
        out2[(((size_t)bv * Hh + h) * Ww + (wb + k)) * 4 + cg] = o;
    }
}

// ---------------------------------------------------------------------------
// Pass 2: project + 5 bilinear samples + gradients.
// Tap-dedup fp16 gathers; interpolation entirely in half2 (HMUL2/HFMA2),
// one conversion to fp32 at the end. Gradient subtraction done in half2
// (exact by Sterbenz for nearby values; x0.5 exact).
// ---------------------------------------------------------------------------
__device__ __forceinline__ void mkpair(float t, int lim,
                                       int& i0, int& i1, float& w0, float& w1) {
    float f0 = floorf(t);
    float a1 = t - f0;          // frac
    float a0 = 1.0f - a1;
    int x0 = (int)f0;
    int x1 = x0 + 1;
    w0 = (x0 >= 0 && x0 < lim) ? a0 : 0.0f;   // mask == reference valid
    w1 = (x1 >= 0 && x1 < lim) ? a1 : 0.0f;
    i0 = min(max(x0, 0), lim - 1);            // == reference clip
    i1 = min(max(x1, 0), lim - 1);
}

struct h2p { __half2 lo, hi; };

__device__ __forceinline__ __half2 tlo(uint2 p) { return *reinterpret_cast<__half2*>(&p.x); }
__device__ __forceinline__ __half2 thi(uint2 p) { return *reinterpret_cast<__half2*>(&p.y); }

// r = w0*t0 + w1*t1   (4 half2 ops)
__device__ __forceinline__ h2p rowmix(__half2 w0, uint2 t0, __half2 w1, uint2 t1) {
    h2p r;
    r.lo = __hfma2(w1, tlo(t1), __hmul2(w0, tlo(t0)));
    r.hi = __hfma2(w1, thi(t1), __hmul2(w0, thi(t0)));
    return r;
}

// s = w0*r0 + w1*r1   (4 half2 ops)
__device__ __forceinline__ h2p sampmix(__half2 w0, h2p r0, __half2 w1, h2p r1) {
    h2p s;
    s.lo = __hfma2(w1, r1.lo, __hmul2(w0, r0.lo));
    s.hi = __hfma2(w1, r1.hi, __hmul2(w0, r0.hi));
    return s;
}

__global__ __launch_bounds__(256) void fgf_kernel(
    const float* __restrict__ pts,   // (B, 3, N)
    const float* __restrict__ Kmat,  // (B, V, 3, 3)
    const float* __restrict__ Emat,  // (B, V, 3, 4)
    float* __restrict__ out)         // [f (BV*C*N)] [f_grad (BV*C*N*2)]
{
    const int lane4 = threadIdx.x & 3;
    const int n  = blockIdx.x * 64 + (threadIdx.x >> 2);
    const int bv = blockIdx.y;
    const int b  = bv / Vv;

    // point
    const float px = __ldg(&pts[((size_t)b * 3 + 0) * Nn + n]);
    const float py = __ldg(&pts[((size_t)b * 3 + 1) * Nn + n]);
    const float pz = __ldg(&pts[((size_t)b * 3 + 2) * Nn + n]);

    const float* E = Emat + (size_t)bv * 12;
    const float* K = Kmat + (size_t)bv * 9;

    const float X = fmaf(__ldg(E + 0), px, fmaf(__ldg(E + 1), py, fmaf(__ldg(E + 2),  pz, __ldg(E + 3))));
    const float Y = fmaf(__ldg(E + 4), px, fmaf(__ldg(E + 5), py, fmaf(__ldg(E + 6),  pz, __ldg(E + 7))));
    const float Z = fmaf(__ldg(E + 8), px, fmaf(__ldg(E + 9), py, fmaf(__ldg(E + 10), pz, __ldg(E + 11))));

    const float invz = 1.0f / Z;
    const float xn = X * invz;
    const float yn = Y * invz;

    const float u = fmaf(__ldg(K + 0), xn, fmaf(__ldg(K + 1), yn, __ldg(K + 2)));
    const float v = fmaf(__ldg(K + 3), xn, fmaf(__ldg(K + 4), yn, __ldg(K + 5)));

    // grid coords + neighbor shifts (match reference op order)
    const float gx = (u - 0.5f) / (float)(Ww - 1) * 2.0f - 1.0f;
    const float gy = (v - 0.5f) / (float)(Hh - 1) * 2.0f - 1.0f;
    const float dx = 2.0f / (float)(Ww - 1);
    const float dy = 2.0f / (float)(Hh - 1);

    const float ixc = ((gx        + 1.0f) * (float)Ww - 1.0f) * 0.5f;
    const float ixl = (((gx - dx) + 1.0f) * (float)Ww - 1.0f) * 0.5f;
    const float ixr = (((gx + dx) + 1.0f) * (float)Ww - 1.0f) * 0.5f;
    const float iyc = ((gy        + 1.0f) * (float)Hh - 1.0f) * 0.5f;
    const float iyt = (((gy - dy) + 1.0f) * (float)Hh - 1.0f) * 0.5f;
    const float iyb = (((gy + dy) + 1.0f) * (float)Hh - 1.0f) * 0.5f;

    int xc0, xc1, xl0, xl1, xr0, xr1;
    int yc0, yc1, yt0, yt1, yb0, yb1;
    float wxc0, wxc1, wxl0, wxl1, wxr0, wxr1;
    float wyc0, wyc1, wyt0, wyt1, wyb0, wyb1;
    mkpair(ixc, Ww, xc0, xc1, wxc0, wxc1);
    mkpair(ixl, Ww, xl0, xl1, wxl0, wxl1);
    mkpair(ixr, Ww, xr0, xr1, wxr0, wxr1);
    mkpair(iyc, Hh, yc0, yc1, wyc0, wyc1);
    mkpair(iyt, Hh, yt0, yt1, wyt0, wyt1);
    mkpair(iyb, Hh, yb0, yb1, wyb0, wyb1);

    // uint2 addressing into (bv, h, w, c): idx = bv*H*W*4 + (y*W+x)*4 + lane4
    const uint2* base = reinterpret_cast<const uint2*>(g_fmT)
                      + (size_t)bv * ((size_t)Hh * Ww * 4) + lane4;
    const int ryc0 = yc0 * (Ww * 4), ryc1 = yc1 * (Ww * 4);
    const int ryt0 = yt0 * (Ww * 4);
    const int ryb1 = yb1 * (Ww * 4);
    const int cxc0 = xc0 * 4, cxc1 = xc1 * 4;
    const int cxl0 = xl0 * 4;
    const int cxr1 = xr1 * 4;

    // --- 12 unconditional unique taps ---
    const uint2 a0 = __ldg(base + ryc0 + cxl0);   // (yc0, xl0)
    const uint2 b0 = __ldg(base + ryc0 + cxc0);   // (yc0, xc0)
    const uint2 c0 = __ldg(base + ryc0 + cxc1);   // (yc0, xc1)
    const uint2 d0 = __ldg(base + ryc0 + cxr1);   // (yc0, xr1)
    const uint2 a1 = __ldg(base + ryc1 + cxl0);   // (yc1, xl0)
    const uint2 b1 = __ldg(base + ryc1 + cxc0);   // (yc1, xc0)
    const uint2 c1 = __ldg(base + ryc1 + cxc1);   // (yc1, xc1)
    const uint2 d1 = __ldg(base + ryc1 + cxr1);   // (yc1, xr1)
    const uint2 t00 = __ldg(base + ryt0 + cxc0);  // (yt0, xc0)
    const uint2 t01 = __ldg(base + ryt0 + cxc1);  // (yt0, xc1)
    const uint2 q10 = __ldg(base + ryb1 + cxc0);  // (yb1, xc0)
    const uint2 q11 = __ldg(base + ryb1 + cxc1);  // (yb1, xc1)

    // --- rare fallback taps (~0.2% each) ---
    uint2 l1_0 = b0, l1_1 = b1;
    if (xl1 != xc0) {
        const int cxl1 = xl1 * 4;
        l1_0 = __ldg(base + ryc0 + cxl1);
        l1_1 = __ldg(base + ryc1 + cxl1);
    }
    uint2 r0_0 = c0, r0_1 = c1;
    if (xr0 != xc1) {
        const int cxr0 = xr0 * 4;
        r0_0 = __ldg(base + ryc0 + cxr0);
        r0_1 = __ldg(base + ryc1 + cxr0);
    }
    uint2 t10 = b0, t11 = c0;
    if (yt1 != yc0) {
        const int ryt1 = yt1 * (Ww * 4);
        t10 = __ldg(base + ryt1 + cxc0);
        t11 = __ldg(base + ryt1 + cxc1);
    }
    uint2 u00 = b1, u01 = c1;
    if (yb0 != yc1) {
        const int ryb0 = yb0 * (Ww * 4);
        u00 = __ldg(base + ryb0 + cxc0);
        u01 = __ldg(base + ryb0 + cxc1);
    }

    // weights -> half2 broadcast
    const __half2 hxl0 = __float2half2_rn(wxl0), hxl1 = __float2half2_rn(wxl1);
    const __half2 hxc0 = __float2half2_rn(wxc0), hxc1 = __float2half2_rn(wxc1);
    const __half2 hxr0 = __float2half2_rn(wxr0), hxr1 = __float2half2_rn(wxr1);
    const __half2 hyc0 = __float2half2_rn(wyc0), hyc1 = __float2half2_rn(wyc1);
    const __half2 hyt0 = __float2half2_rn(wyt0), hyt1 = __float2half2_rn(wyt1);
    const __half2 hyb0 = __float2half2_rn(wyb0), hyb1 = __float2half2_rn(wyb1);

    // x-mixed rows (10 rows x 4 half2 ops)
    const h2p L0 = rowmix(hxl0, a0,   hxl1, l1_0);
    const h2p L1 = rowmix(hxl0, a1,   hxl1, l1_1);
    const h2p C0 = rowmix(hxc0, b0,   hxc1, c0);
    const h2p C1 = rowmix(hxc0, b1,   hxc1, c1);
    const h2p R0 = rowmix(hxr0, r0_0, hxr1, d0);
    const h2p R1 = rowmix(hxr0, r0_1, hxr1, d1);
    const h2p T0 = rowmix(hxc0, t00,  hxc1, t01);
    const h2p T1 = rowmix(hxc0, t10,  hxc1, t11);   // == C0 in common case
    const h2p B0 = rowmix(hxc0, u00,  hxc1, u01);   // == C1 in common case
    const h2p B1 = rowmix(hxc0, q10,  hxc1, q11);

    // y-mixed samples (5 x 4 half2 ops)
    const h2p F  = sampmix(hyc0, C0, hyc1, C1);
    const h2p FL = sampmix(hyc0, L0, hyc1, L1);
    const h2p FR = sampmix(hyc0, R0, hyc1, R1);
    const h2p FT = sampmix(hyt0, T0, hyt1, T1);
    const h2p FB = sampmix(hyb0, B0, hyb1, B1);

    // gradients in half2 (Sterbenz-exact sub of nearby values; x0.5 exact)
    const __half2 h05 = __float2half2_rn(0.5f);
    const __half2 gxlo = __hmul2(h05, __hsub2(FR.lo, FL.lo));
    const __half2 gxhi = __hmul2(h05, __hsub2(FR.hi, FL.hi));
    const __half2 gylo = __hmul2(h05, __hsub2(FB.lo, FT.lo));
    const __half2 gyhi = __hmul2(h05, __hsub2(FB.hi, FT.hi));

    // convert to fp32 for output
    const float2 Flo = __half22float2(F.lo),  Fhi = __half22float2(F.hi);
    const float2 Xlo = __half22float2(gxlo), Xhi = __half22float2(gxhi);
    const float2 Ylo = __half22float2(gylo), Yhi = __half22float2(gyhi);

    // f output: (bv, c, n); this lane owns channels lane4*4 .. +3
    const size_t fb = ((size_t)bv * Cch + (size_t)lane4 * 4) * Nn + n;
    __stcs(&out[fb + 0 * (size_t)Nn], Flo.x);
    __stcs(&out[fb + 1 * (size_t)Nn], Flo.y);
    __stcs(&out[fb + 2 * (size_t)Nn], Fhi.x);
    __stcs(&out[fb + 3 * (size_t)Nn], Fhi.y);

    // f_grad output: (bv, c, n, 2) -> float2 per (c, n)
    float2* og = reinterpret_cast<float2*>(out + (size_t)BV * Cch * Nn)
               + ((size_t)bv * Cch + (size_t)lane4 * 4) * Nn + n;
    __stcs(&og[0 * (size_t)Nn], make_float2(Xlo.x, Ylo.x));
    __stcs(&og[1 * (size_t)Nn], make_float2(Xlo.y, Ylo.y));
    __stcs(&og[2 * (size_t)Nn], make_float2(Xhi.x, Yhi.x));
    __stcs(&og[3 * (size_t)Nn], make_float2(Xhi.y, Yhi.y));
}

// ---------------------------------------------------------------------------
extern "C" void kernel_launch(void* const* d_in, const int* in_sizes, int n_in,
                              void* d_out, int out_size) {
    // Identify inputs robustly by element count.
    const float* fm  = nullptr;
    const float* pts = nullptr;
    const float* K   = nullptr;
    const float* E   = nullptr;
    for (int i = 0; i < n_in; i++) {
        switch (in_sizes[i]) {
            case Bb * Vv * Cch * Hh * Ww: fm  = (const float*)d_in[i]; break;  // 52428800
            case Bb * 3 * Nn:             pts = (const float*)d_in[i]; break;  // 786432
            case Bb * Vv * 9:             K   = (const float*)d_in[i]; break;  // 90
            case Bb * Vv * 12:            E   = (const float*)d_in[i]; break;  // 120
            default: break;
        }
    }

    dim3 tg(Ww / 64, Hh / 2, BV);
    transpose_kernel<<<tg, 256>>>(fm);

    dim3 mg(Nn / 64, BV);
    fgf_kernel<<<mg, 256>>>(pts, K, E, (float*)d_out);
}